// round 16
// baseline (speedup 1.0000x reference)
#include <cuda_runtime.h>
#include <float.h>

#define Bn 4
#define Nn 16384
#define Sn 4096
#define Cin 256
#define Cout 256

#define SPLITS 4
#define SCHUNK (Sn / SPLITS)   // 1024 candidates per CTA
#define NPAIR  (SCHUNK / 2)    // 512 candidate pairs (16 KB table)

typedef unsigned long long u64;

__device__ __forceinline__ u64 pack2(float x, float y) {
    u64 r; asm("mov.b64 %0, {%1,%2};" : "=l"(r) : "f"(x), "f"(y)); return r;
}
__device__ __forceinline__ void unpack2(u64 v, float& x, float& y) {
    asm("mov.b64 {%0,%1}, %2;" : "=f"(x), "=f"(y) : "l"(v));
}
__device__ __forceinline__ u64 ffma2(u64 a, u64 b, u64 c) {
    u64 d; asm("fma.rn.f32x2 %0, %1, %2, %3;" : "=l"(d) : "l"(a), "l"(b), "l"(c)); return d;
}

// Scratch (device globals -- allocation-free per harness rules)
__device__ float g_G[Bn * Sn * Cout];            // [b][s][o], 16.8 MB
__device__ float g_pd[SPLITS * Bn * Nn * 3];     // partial top-3 rank values
__device__ int   g_pi[SPLITS * Bn * Nn * 3];     // partial top-3 indices

// ---------------------------------------------------------------------------
// K1: G[b][s][o] = sum_c P[b][c][s] * W[o][c] + bias[o]
// 128x128 tile, K-step 8, f32x2 packed FMA, double-buffered. (58us proven.)
// BYTE-IDENTICAL to R13.
// ---------------------------------------------------------------------------
__global__ __launch_bounds__(256, 2) void k1_gemm(const float* __restrict__ P,
                                                  const float* __restrict__ W,
                                                  const float* __restrict__ bias) {
    __shared__ float sP[2][8][128];
    __shared__ float sW[2][8][128];

    const int b  = blockIdx.z;
    const int s0 = blockIdx.x * 128;
    const int o0 = blockIdx.y * 128;
    const int tid = threadIdx.x;
    const int txo = tid & 15;
    const int tys = tid >> 4;
    const int obase = txo * 8;
    const int sbase = tys * 8;

    const float* Pb = P + b * Cin * Sn;

    const int lk  = tid >> 5;
    const int ls4 = (tid & 31) * 4;
    const int wo  = tid >> 1;
    const int wk  = (tid & 1) * 4;

    u64 acc[8][4];
#pragma unroll
    for (int i = 0; i < 8; i++)
#pragma unroll
        for (int j = 0; j < 4; j++) acc[i][j] = 0ull;

    float4 pA = *(const float4*)&Pb[lk * Sn + s0 + ls4];
    float4 pW = *(const float4*)&W[(o0 + wo) * Cin + wk];
    *(float4*)&sP[0][lk][ls4] = pA;
    sW[0][wk + 0][wo] = pW.x;
    sW[0][wk + 1][wo] = pW.y;
    sW[0][wk + 2][wo] = pW.z;
    sW[0][wk + 3][wo] = pW.w;
    __syncthreads();

    for (int step = 0; step < 32; step++) {
        const int cur = step & 1;
        const int nxt = cur ^ 1;
        if (step < 31) {
            const int k0 = (step + 1) * 8;
            pA = *(const float4*)&Pb[(k0 + lk) * Sn + s0 + ls4];
            pW = *(const float4*)&W[(o0 + wo) * Cin + k0 + wk];
        }

#pragma unroll
        for (int k = 0; k < 8; k++) {
            const ulonglong2 w01 = *(const ulonglong2*)&sW[cur][k][obase];
            const ulonglong2 w23 = *(const ulonglong2*)&sW[cur][k][obase + 4];
            const float4 a0 = *(const float4*)&sP[cur][k][sbase];
            const float4 a1 = *(const float4*)&sP[cur][k][sbase + 4];
            const u64 ad[8] = {pack2(a0.x, a0.x), pack2(a0.y, a0.y),
                               pack2(a0.z, a0.z), pack2(a0.w, a0.w),
                               pack2(a1.x, a1.x), pack2(a1.y, a1.y),
                               pack2(a1.z, a1.z), pack2(a1.w, a1.w)};
            const u64 wv[4] = {w01.x, w01.y, w23.x, w23.y};
#pragma unroll
            for (int i = 0; i < 8; i++)
#pragma unroll
                for (int j = 0; j < 4; j++)
                    acc[i][j] = ffma2(ad[i], wv[j], acc[i][j]);
        }

        if (step < 31) {
            *(float4*)&sP[nxt][lk][ls4] = pA;
            sW[nxt][wk + 0][wo] = pW.x;
            sW[nxt][wk + 1][wo] = pW.y;
            sW[nxt][wk + 2][wo] = pW.z;
            sW[nxt][wk + 3][wo] = pW.w;
        }
        __syncthreads();
    }

    float* Gb = g_G + b * Sn * Cout;
    const float4 bb0 = *(const float4*)&bias[o0 + obase];
    const float4 bb1 = *(const float4*)&bias[o0 + obase + 4];
#pragma unroll
    for (int i = 0; i < 8; i++) {
        const float2 p0 = *(float2*)&acc[i][0];
        const float2 p1 = *(float2*)&acc[i][1];
        const float2 p2 = *(float2*)&acc[i][2];
        const float2 p3 = *(float2*)&acc[i][3];
        float4 v0, v1;
        v0.x = p0.x + bb0.x; v0.y = p0.y + bb0.y;
        v0.z = p1.x + bb0.z; v0.w = p1.y + bb0.w;
        v1.x = p2.x + bb1.x; v1.y = p2.y + bb1.y;
        v1.z = p3.x + bb1.z; v1.w = p3.y + bb1.w;
        float* row = &Gb[(s0 + sbase + i) * Cout + o0 + obase];
        *(float4*)&row[0] = v0;
        *(float4*)&row[4] = v1;
    }
}

// ---------------------------------------------------------------------------
// K2a: partial 3-NN over one S-chunk. 2 points/thread (lists A,B) sharing
// candidate-pair f32x2 table loads and ONE min-gate per 4-candidate group.
// SPLITS=4: grid (Nn/512, 4, Bn) = 512 CTAs, 16 KB table (occupancy kept).
// Inserts ascending-s per list -> tie-break preserved.
// ---------------------------------------------------------------------------
struct QP { ulonglong2 xy; ulonglong2 zw; };   // xy={xx,yy}, zw={zz,ww}; 32B

__global__ __launch_bounds__(256) void k2_partial(const float* __restrict__ xyz1,
                                                  const float* __restrict__ xyz2) {
    __shared__ QP qtab[NPAIR];   // 16 KB

    const int b   = blockIdx.z;
    const int sp  = blockIdx.y;
    const int n0  = blockIdx.x * 512;
    const int tid = threadIdx.x;
    const int sb  = sp * SCHUNK;

    const float* x2 = xyz2 + b * 3 * Sn;
    for (int p = tid; p < NPAIR; p += 256) {
        const float2 x01 = *(const float2*)&x2[sb + 2 * p];
        const float2 y01 = *(const float2*)&x2[Sn + sb + 2 * p];
        const float2 z01 = *(const float2*)&x2[2 * Sn + sb + 2 * p];
        QP q;
        q.xy.x = pack2(-2.f * x01.x, -2.f * x01.y);
        q.xy.y = pack2(-2.f * y01.x, -2.f * y01.y);
        q.zw.x = pack2(-2.f * z01.x, -2.f * z01.y);
        q.zw.y = pack2(x01.x * x01.x + y01.x * y01.x + z01.x * z01.x,
                       x01.y * x01.y + y01.y * y01.y + z01.y * z01.y);
        qtab[p] = q;
    }
    __syncthreads();

    const int nA = n0 + tid;
    const int nB = nA + 256;
    const float* x1 = xyz1 + b * 3 * Nn;
    const float pxA = x1[nA], pyA = x1[Nn + nA], pzA = x1[2 * Nn + nA];
    const float pxB = x1[nB], pyB = x1[Nn + nB], pzB = x1[2 * Nn + nB];
    const u64 pxxA = pack2(pxA, pxA), pyyA = pack2(pyA, pyA), pzzA = pack2(pzA, pzA);
    const u64 pxxB = pack2(pxB, pxB), pyyB = pack2(pyB, pyB), pzzB = pack2(pzB, pzB);

    float d0A = FLT_MAX, d1A = FLT_MAX, d2A = FLT_MAX;
    float d0B = FLT_MAX, d1B = FLT_MAX, d2B = FLT_MAX;
    int   i0A = 0, i1A = 0, i2A = 0;
    int   i0B = 0, i1B = 0, i2B = 0;

#pragma unroll 2
    for (int g = 0; g < NPAIR; g += 2) {   // 2 pairs = 4 candidates, 8 evals
        const ulonglong2 Uxy = qtab[g].xy;
        const ulonglong2 Uzw = qtab[g].zw;
        const ulonglong2 Vxy = qtab[g + 1].xy;
        const ulonglong2 Vzw = qtab[g + 1].zw;
        // point A vs pairs U,V
        u64 aU = ffma2(pzzA, Uzw.x, Uzw.y);
        u64 aV = ffma2(pzzA, Vzw.x, Vzw.y);
        // point B vs pairs U,V (reuses same table regs)
        u64 bU = ffma2(pzzB, Uzw.x, Uzw.y);
        u64 bV = ffma2(pzzB, Vzw.x, Vzw.y);
        aU = ffma2(pyyA, Uxy.y, aU);
        aV = ffma2(pyyA, Vxy.y, aV);
        bU = ffma2(pyyB, Uxy.y, bU);
        bV = ffma2(pyyB, Vxy.y, bV);
        aU = ffma2(pxxA, Uxy.x, aU);
        aV = ffma2(pxxA, Vxy.x, aV);
        bU = ffma2(pxxB, Uxy.x, bU);
        bV = ffma2(pxxB, Vxy.x, bV);
        float a0, a1, a2, a3, b0, b1, b2, b3;
        unpack2(aU, a0, a1);
        unpack2(aV, a2, a3);
        unpack2(bU, b0, b1);
        unpack2(bV, b2, b3);
        const float mA = fminf(fminf(a0, a1), fminf(a2, a3));
        const float mB = fminf(fminf(b0, b1), fminf(b2, b3));
        if ((mA < d2A) | (mB < d2B)) {
            const float ea[4] = {a0, a1, a2, a3};
            const float eb[4] = {b0, b1, b2, b3};
            if (mA < d2A) {
#pragma unroll
                for (int j = 0; j < 4; j++) {
                    const float e = ea[j];
                    if (e < d2A) {
                        const int gs = sb + 2 * g + j;
                        if (e < d0A)      { d2A = d1A; i2A = i1A; d1A = d0A; i1A = i0A; d0A = e; i0A = gs; }
                        else if (e < d1A) { d2A = d1A; i2A = i1A; d1A = e;  i1A = gs; }
                        else              { d2A = e;  i2A = gs; }
                    }
                }
            }
            if (mB < d2B) {
#pragma unroll
                for (int j = 0; j < 4; j++) {
                    const float e = eb[j];
                    if (e < d2B) {
                        const int gs = sb + 2 * g + j;
                        if (e < d0B)      { d2B = d1B; i2B = i1B; d1B = d0B; i1B = i0B; d0B = e; i0B = gs; }
                        else if (e < d1B) { d2B = d1B; i2B = i1B; d1B = e;  i1B = gs; }
                        else              { d2B = e;  i2B = gs; }
                    }
                }
            }
        }
    }

    const int baseA = ((sp * Bn + b) * Nn + nA) * 3;
    g_pd[baseA + 0] = d0A; g_pd[baseA + 1] = d1A; g_pd[baseA + 2] = d2A;
    g_pi[baseA + 0] = i0A; g_pi[baseA + 1] = i1A; g_pi[baseA + 2] = i2A;
    const int baseB = ((sp * Bn + b) * Nn + nB) * 3;
    g_pd[baseB + 0] = d0B; g_pd[baseB + 1] = d1B; g_pd[baseB + 2] = d2B;
    g_pi[baseB + 0] = i0B; g_pi[baseB + 1] = i1B; g_pi[baseB + 2] = i2B;
}

// ---------------------------------------------------------------------------
// K3: fused merge + gather + weighted sum + transpose-write.
// BYTE-IDENTICAL to R13 (merge loop adapts via SPLITS macro).
// ---------------------------------------------------------------------------
#define ACC_PITCH 261

__global__ __launch_bounds__(256) void k3_gather(const float* __restrict__ xyz1,
                                                 float* __restrict__ out) {
    extern __shared__ unsigned char smem_raw[];
    float* acc = (float*)smem_raw;            // [64][ACC_PITCH]
    __shared__ float sw[64 * 3];
    __shared__ int   si[64 * 3];

    const int b   = blockIdx.y;
    const int n0  = blockIdx.x * 64;
    const int tid = threadIdx.x;

    // merge phase: one thread per point
    if (tid < 64) {
        const int n = n0 + tid;
        float d0 = FLT_MAX, d1 = FLT_MAX, d2 = FLT_MAX;
        int   i0 = 0, i1 = 0, i2 = 0;
#pragma unroll
        for (int sp = 0; sp < SPLITS; sp++) {
            const int base = ((sp * Bn + b) * Nn + n) * 3;
#pragma unroll
            for (int r = 0; r < 3; r++) {
                const float e  = g_pd[base + r];
                const int   id = g_pi[base + r];
                if (e < d2) {
                    if (e < d0)      { d2 = d1; i2 = i1; d1 = d0; i1 = i0; d0 = e; i0 = id; }
                    else if (e < d1) { d2 = d1; i2 = i1; d1 = e;  i1 = id; }
                    else             { d2 = e;  i2 = id; }
                }
            }
        }
        const float* x1 = xyz1 + b * 3 * Nn;
        const float px = x1[n], py = x1[Nn + n], pz = x1[2 * Nn + n];
        const float pn = px * px + py * py + pz * pz;
        const float r0 = 1.f / (d0 + pn + 1e-8f);
        const float r1 = 1.f / (d1 + pn + 1e-8f);
        const float r2 = 1.f / (d2 + pn + 1e-8f);
        const float inv = 1.f / (r0 + r1 + r2);
        sw[3 * tid + 0] = r0 * inv;
        sw[3 * tid + 1] = r1 * inv;
        sw[3 * tid + 2] = r2 * inv;
        si[3 * tid + 0] = i0;
        si[3 * tid + 1] = i1;
        si[3 * tid + 2] = i2;
    }
    __syncthreads();

    const float* Gb = g_G + b * Sn * Cout;
    const int grp = tid >> 6;        // 0..3
    const int lane = tid & 63;       // 0..63 -> channels 4*lane..4*lane+3

#pragma unroll 2
    for (int p = grp; p < 64; p += 4) {
        const float w0 = sw[3 * p + 0];
        const float w1 = sw[3 * p + 1];
        const float w2 = sw[3 * p + 2];
        const int   j0 = si[3 * p + 0];
        const int   j1 = si[3 * p + 1];
        const int   j2 = si[3 * p + 2];
        const float4 a0 = *((const float4*)(Gb + j0 * Cout) + lane);
        const float4 a1 = *((const float4*)(Gb + j1 * Cout) + lane);
        const float4 a2 = *((const float4*)(Gb + j2 * Cout) + lane);
        float4 v;
        v.x = fmaf(w2, a2.x, fmaf(w1, a1.x, w0 * a0.x));
        v.y = fmaf(w2, a2.y, fmaf(w1, a1.y, w0 * a0.y));
        v.z = fmaf(w2, a2.z, fmaf(w1, a1.z, w0 * a0.z));
        v.w = fmaf(w2, a2.w, fmaf(w1, a1.w, w0 * a0.w));
        float* d = &acc[p * ACC_PITCH + 4 * lane];
        d[0] = v.x; d[1] = v.y; d[2] = v.z; d[3] = v.w;
    }
    __syncthreads();

    float* ob = out + b * Cout * Nn;
    for (int idx = tid; idx < 256 * 16; idx += 256) {
        const int c = idx >> 4;
        const int g = idx & 15;
        float4 v;
        v.x = acc[(4 * g + 0) * ACC_PITCH + c];
        v.y = acc[(4 * g + 1) * ACC_PITCH + c];
        v.z = acc[(4 * g + 2) * ACC_PITCH + c];
        v.w = acc[(4 * g + 3) * ACC_PITCH + c];
        *(float4*)&ob[c * Nn + n0 + 4 * g] = v;
    }
}

// ---------------------------------------------------------------------------
extern "C" void kernel_launch(void* const* d_in, const int* in_sizes, int n_in,
                              void* d_out, int out_size) {
    const float* xyz1 = (const float*)d_in[0];   // [B,3,N]
    const float* xyz2 = (const float*)d_in[1];   // [B,3,S]
    const float* P    = (const float*)d_in[2];   // [B,Cin,S]
    const float* W    = (const float*)d_in[3];   // [Cout,Cin]
    const float* bias = (const float*)d_in[4];   // [Cout]
    float* out = (float*)d_out;                  // [B,Cout,N]

    cudaFuncSetAttribute(k3_gather, cudaFuncAttributeMaxDynamicSharedMemorySize,
                         64 * ACC_PITCH * (int)sizeof(float));

    k1_gemm<<<dim3(Sn / 128, Cout / 128, Bn), 256>>>(P, W, bias);
    k2_partial<<<dim3(Nn / 512, SPLITS, Bn), 256>>>(xyz1, xyz2);
    k3_gather<<<dim3(Nn / 64, Bn), 256, 64 * ACC_PITCH * sizeof(float)>>>(xyz1, out);
}